// round 17
// baseline (speedup 1.0000x reference)
#include <cuda_runtime.h>
#include <cuda_fp16.h>
#include <math.h>
#include <stdint.h>

#define BB 4
#define TT 2048
#define CC 1024
#define HH 16
#define DHD 64
#define MM (BB*TT)          // 8192
#define WSZ (HH*CC*DHD)     // 1048576
#define NX (MM*CC)          // 8388608
#define NTOT (NX + 3*WSZ + CC*CC)   // 12582912

// Scratch (allocation-free rule: __device__ globals), all fp16
__device__ __align__(16) __half g_q[BB*HH*TT*DHD];   // pre-scaled by dh^-.5*log2e
__device__ __align__(16) __half g_k[BB*HH*TT*DHD];
__device__ __align__(16) __half g_v[BB*HH*TT*DHD];
__device__ __align__(16) __half g_o[BB*HH*TT*DHD];   // attn out
__device__ __align__(16) __half g_xh[NX];            // x
__device__ __align__(16) __half g_wh[3*WSZ];         // Wq|Wk|Wv ([h][c][d] layout)
__device__ __align__(16) __half g_woh[CC*CC];        // Wo rows [n][k]

// ---------------------------------------------------------------------------
// helpers
// ---------------------------------------------------------------------------
__device__ __forceinline__ void cp16(void* s, const void* g) {
    uint32_t sa = (uint32_t)__cvta_generic_to_shared(s);
    asm volatile("cp.async.cg.shared.global [%0], [%1], 16;" :: "r"(sa), "l"(g));
}
#define CP_COMMIT() asm volatile("cp.async.commit_group;")
#define CP_WAIT(N)  asm volatile("cp.async.wait_group %0;" :: "n"(N))

__device__ __forceinline__ uint32_t h2u(float a, float b) {
    __half2 h = __floats2half2_rn(a, b);
    return *(uint32_t*)&h;
}
__device__ __forceinline__ uint32_t ex2h2(uint32_t a) {
    uint32_t d;
    asm("ex2.approx.f16x2 %0, %1;" : "=r"(d) : "r"(a));
    return d;
}
__device__ __forceinline__ uint32_t addh2(uint32_t a, uint32_t b) {
    uint32_t d;
    asm("add.rn.f16x2 %0, %1, %2;" : "=r"(d) : "r"(a), "r"(b));
    return d;
}
// additive causal mask: 0 where col<=row, -inf(f16) where masked
__device__ __forceinline__ uint32_t mk_mask(int col0, int row) {
    uint32_t lo = (col0     <= row) ? 0u : 0xFC00u;
    uint32_t hi = (col0 + 1 <= row) ? 0u : 0xFC00u;
    return lo | (hi << 16);
}
// D += A(16x16)*B(16x8), fp16 in, fp32 acc
__device__ __forceinline__ void mma16(float* c, const uint32_t* a, const uint32_t* b) {
    asm volatile(
        "mma.sync.aligned.m16n8k16.row.col.f32.f16.f16.f32 "
        "{%0,%1,%2,%3}, {%4,%5,%6,%7}, {%8,%9}, {%0,%1,%2,%3};"
        : "+f"(c[0]), "+f"(c[1]), "+f"(c[2]), "+f"(c[3])
        : "r"(a[0]), "r"(a[1]), "r"(a[2]), "r"(a[3]), "r"(b[0]), "r"(b[1]));
}
// D += A(16x16)*B(16x8), fp16 in, fp16 acc (D = 2 packed half2 regs)
__device__ __forceinline__ void mma16h(uint32_t* d, const uint32_t* a, const uint32_t* b) {
    asm volatile(
        "mma.sync.aligned.m16n8k16.row.col.f16.f16.f16.f16 "
        "{%0,%1}, {%2,%3,%4,%5}, {%6,%7}, {%0,%1};"
        : "+r"(d[0]), "+r"(d[1])
        : "r"(a[0]), "r"(a[1]), "r"(a[2]), "r"(a[3]), "r"(b[0]), "r"(b[1]));
}
__device__ __forceinline__ void ldsm_x4(uint32_t& r0, uint32_t& r1, uint32_t& r2,
                                        uint32_t& r3, const __half* p) {
    uint32_t addr = (uint32_t)__cvta_generic_to_shared(p);
    asm volatile("ldmatrix.sync.aligned.m8n8.x4.shared.b16 {%0,%1,%2,%3}, [%4];"
                 : "=r"(r0), "=r"(r1), "=r"(r2), "=r"(r3) : "r"(addr));
}
__device__ __forceinline__ void ldsm_x4_trans(uint32_t& r0, uint32_t& r1, uint32_t& r2,
                                              uint32_t& r3, const __half* p) {
    uint32_t addr = (uint32_t)__cvta_generic_to_shared(p);
    asm volatile("ldmatrix.sync.aligned.m8n8.x4.trans.shared.b16 {%0,%1,%2,%3}, [%4];"
                 : "=r"(r0), "=r"(r1), "=r"(r2), "=r"(r3) : "r"(addr));
}

// ---------------------------------------------------------------------------
// Kernel 0: single fused fp32->fp16 prepass (x | Wq | Wk | Wv | Wo).
// ---------------------------------------------------------------------------
__global__ __launch_bounds__(256) void cvt_all(const float* __restrict__ x,
                                               const float* __restrict__ wq,
                                               const float* __restrict__ wk,
                                               const float* __restrict__ wv,
                                               const float* __restrict__ wo)
{
    size_t i = ((size_t)blockIdx.x * 256 + threadIdx.x) * 16;
    const float* src; __half* dst; size_t off;
    if (i < NX)                       { src = x;  dst = g_xh;         off = i; }
    else if (i < NX + (size_t)WSZ)    { src = wq; dst = g_wh;         off = i - NX; }
    else if (i < NX + 2*(size_t)WSZ)  { src = wk; dst = g_wh + WSZ;   off = i - NX - WSZ; }
    else if (i < NX + 3*(size_t)WSZ)  { src = wv; dst = g_wh + 2*WSZ; off = i - NX - 2*WSZ; }
    else                              { src = wo; dst = g_woh;        off = i - NX - 3*WSZ; }
    float4 v0 = *(const float4*)&src[off];
    float4 v1 = *(const float4*)&src[off + 4];
    float4 v2 = *(const float4*)&src[off + 8];
    float4 v3 = *(const float4*)&src[off + 12];
    uint4 o0, o1;
    o0.x = h2u(v0.x, v0.y); o0.y = h2u(v0.z, v0.w);
    o0.z = h2u(v1.x, v1.y); o0.w = h2u(v1.z, v1.w);
    o1.x = h2u(v2.x, v2.y); o1.y = h2u(v2.z, v2.w);
    o1.z = h2u(v3.x, v3.y); o1.w = h2u(v3.z, v3.w);
    *(uint4*)&dst[off]     = o0;
    *(uint4*)&dst[off + 8] = o1;
}

// ---------------------------------------------------------------------------
// Kernel 1: merged QKV GEMM, fp16 m16n8k16, K-chunk 64, 3-stage cp.async.
// 256 threads (8 warps, 2x4; warp tile 64x32). (unchanged)
// ---------------------------------------------------------------------------
#define QKV_ABUF (128*72)
#define QKV_BBUF (64*136)
#define QKV_SMEM (3 * (QKV_ABUF + QKV_BBUF) * (int)sizeof(__half))   // 107520

__global__ __launch_bounds__(256, 2) void qkv_kernel()
{
    const int m0 = blockIdx.x * 128;
    const int by = blockIdx.y;
    const int z  = by >> 3;
    const int h0 = (by & 7) * 2;
    const __half* Wh = g_wh + (size_t)z * WSZ;   // [h][c][d]
    __half* out = (z == 0 ? g_q : (z == 1 ? g_k : g_v));

    extern __shared__ __half smh[];
    __half* As = smh;                       // [3][128][72]
    __half* Bs = smh + 3 * QKV_ABUF;        // [3][64][136]

    const int tid  = threadIdx.x;
    const int wid  = tid >> 5, lane = tid & 31;
    const int wm   = wid >> 2, wn = wid & 3;      // 2 x 4 warp grid
    const int g    = lane >> 2, t4 = lane & 3;
    const int mi   = lane >> 3, mr = lane & 7;

    float c[4][4][4] = {};

    auto stage = [&](int buf, int kk0) {
        __half* Ab = As + buf * QKV_ABUF;
        __half* Bb = Bs + buf * QKV_BBUF;
        #pragma unroll
        for (int i = 0; i < 4; i++) {
            int f = tid + 256 * i;
            int r = f >> 3, q = (f & 7) * 8;
            cp16(&Ab[r * 72 + q], &g_xh[(size_t)(m0 + r) * CC + kk0 + q]);
        }
        #pragma unroll
        for (int i = 0; i < 4; i++) {
            int f = tid + 256 * i;
            int r = f >> 4, q = (f & 15) * 8;
            cp16(&Bb[r * 136 + q],
                 &Wh[((size_t)(h0 + (q >> 6)) * CC + kk0 + r) * DHD + (q & 63)]);
        }
    };

    stage(0, 0);   CP_COMMIT();
    stage(1, 64);  CP_COMMIT();

    int cur = 0, nxt = 2;
    for (int t = 0; t < 16; t++) {
        if (t < 15) { CP_WAIT(1); } else { CP_WAIT(0); }
        __syncthreads();
        if (t + 2 < 16) { stage(nxt, (t + 2) * 64); CP_COMMIT(); }

        const __half* Ab = As + cur * QKV_ABUF;
        const __half* Bb = Bs + cur * QKV_BBUF;
        #pragma unroll
        for (int ks = 0; ks < 4; ks++) {
            uint32_t a[4][4], b[4][2];
            #pragma unroll
            for (int mf = 0; mf < 4; mf++) {
                int row = wm * 64 + mf * 16 + (mi & 1) * 8 + mr;
                int ko  = ks * 16 + (mi >> 1) * 8;
                ldsm_x4(a[mf][0], a[mf][1], a[mf][2], a[mf][3], &Ab[row * 72 + ko]);
            }
            #pragma unroll
            for (int p = 0; p < 2; p++) {
                int krow = ks * 16 + (mi & 1) * 8 + mr;
                int col  = wn * 32 + (2 * p + (mi >> 1)) * 8;
                ldsm_x4_trans(b[2*p][0], b[2*p][1], b[2*p+1][0], b[2*p+1][1],
                              &Bb[krow * 136 + col]);
            }
            #pragma unroll
            for (int mf = 0; mf < 4; mf++)
                #pragma unroll
                for (int nf = 0; nf < 4; nf++)
                    mma16(c[mf][nf], a[mf], b[nf]);
        }
        cur = (cur == 2) ? 0 : cur + 1;
        nxt = (nxt == 2) ? 0 : nxt + 1;
    }

    const int h  = h0 + (wn >> 1);
    const int db = (wn & 1) * 32;
    const float osc = (z == 0) ? 0.125f * 1.4426950408889634f : 1.0f;
    #pragma unroll
    for (int mf = 0; mf < 4; mf++) {
        int m1 = m0 + wm * 64 + mf * 16 + g;
        int m2 = m1 + 8;
        int b1 = m1 >> 11, t1 = m1 & (TT - 1);
        int b2 = m2 >> 11, t2 = m2 & (TT - 1);
        __half* d1 = out + ((size_t)(b1 * HH + h) * TT + t1) * DHD;
        __half* d2 = out + ((size_t)(b2 * HH + h) * TT + t2) * DHD;
        #pragma unroll
        for (int nf = 0; nf < 4; nf++) {
            int d = db + nf * 8 + 2 * t4;
            *(uint32_t*)&d1[d] = h2u(c[mf][nf][0] * osc, c[mf][nf][1] * osc);
            *(uint32_t*)&d2[d] = h2u(c[mf][nf][2] * osc, c[mf][nf][3] * osc);
        }
    }
}

// ---------------------------------------------------------------------------
// Kernel 2: causal flash attention. 256 threads: 8 warps x 16 rows of a
// 128-row q-tile (4 warps/SMSP). S-GEMM fp16-acc, K/V double-buffered,
// one wait + one barrier per chunk. Same arithmetic as R16 per row.
// ---------------------------------------------------------------------------
#define ATTN_SMEM ((4*64*72) * (int)sizeof(__half))   // 36864

__global__ __launch_bounds__(256, 2) void attn_kernel()
{
    const int qt = gridDim.x - 1 - blockIdx.x;   // heavy tiles first
    const int bh = blockIdx.y;
    const __half* qb = g_q + (size_t)bh * TT * DHD;
    const __half* kb = g_k + (size_t)bh * TT * DHD;
    const __half* vb = g_v + (size_t)bh * TT * DHD;
    __half* ob = g_o + (size_t)bh * TT * DHD;

    extern __shared__ __half smh[];
    __half* Kb = smh;                   // [2][64][72]
    __half* Vb = smh + 2 * 64 * 72;     // [2][64][72]

    const int tid  = threadIdx.x;
    const int wid  = tid >> 5, lane = tid & 31;
    const int g    = lane >> 2, t4 = lane & 3;
    const int mi   = lane >> 3, mr = lane & 7;
    const int rb   = wid * 16;          // 16 rows per warp
    const int q0   = qt * 128;

    // stage Q (128 x 64 halves) into smh, pull this warp's frags to regs
    #pragma unroll
    for (int i = 0; i < 4; i++) {
        int f = tid + 256 * i;
        int r = f >> 3, q = (f & 7) * 8;
        cp16(&smh[r * 72 + q], &qb[(size_t)(q0 + r) * DHD + q]);
    }
    CP_COMMIT(); CP_WAIT(0); __syncthreads();

    uint32_t qf[4][4];
    #pragma unroll
    for (int ks = 0; ks < 4; ks++) {
        int row = rb + (mi & 1) * 8 + mr;
        int ko  = ks * 16 + (mi >> 1) * 8;
        ldsm_x4(qf[ks][0], qf[ks][1], qf[ks][2], qf[ks][3], &smh[row * 72 + ko]);
    }
    __syncthreads();   // done reading Q before K_0 overwrites

    // stage K_0 + V_0
    #pragma unroll
    for (int i = 0; i < 2; i++) {
        int f = tid + 256 * i;
        int r = f >> 3, q = (f & 7) * 8;
        cp16(&Kb[r * 72 + q], &kb[(size_t)r * DHD + q]);
        cp16(&Vb[r * 72 + q], &vb[(size_t)r * DHD + q]);
    }
    CP_COMMIT(); CP_WAIT(0); __syncthreads();

    float o[8][4] = {};
    float lacc[4] = {};
    const uint32_t ONES2 = 0x3C003C00u;
    const uint32_t bones[2] = {ONES2, ONES2};

    const int n = 2 * qt + 2;
    for (int j = 0; j < n; ++j) {
        const int k0 = j * 64;

        if (j + 1 < n) {
            #pragma unroll
            for (int i = 0; i < 2; i++) {
                int f = tid + 256 * i;
                int r = f >> 3, q = (f & 7) * 8;
                cp16(&Kb[((j + 1) & 1) * 64 * 72 + r * 72 + q],
                     &kb[(size_t)(k0 + 64 + r) * DHD + q]);
                cp16(&Vb[((j + 1) & 1) * 64 * 72 + r * 72 + q],
                     &vb[(size_t)(k0 + 64 + r) * DHD + q]);
            }
        }
        CP_COMMIT();

        const bool act = (k0 <= q0 + rb + 15);
        const __half* Kc = Kb + (j & 1) * 64 * 72;
        const __half* Vc = Vb + (j & 1) * 64 * 72;

        if (act) {
            uint32_t pa[4][4];
            // S = Q K^T (fp16 acc), additive mask + ex2.f16x2 -> PV A-frags
            #pragma unroll
            for (int pp = 0; pp < 4; pp++) {
                uint32_t s0h[2] = {0u, 0u}, s1h[2] = {0u, 0u};
                #pragma unroll
                for (int ks = 0; ks < 4; ks++) {
                    uint32_t bk[4];
                    int row = pp * 16 + (mi >> 1) * 8 + mr;
                    int ko  = ks * 16 + (mi & 1) * 8;
                    ldsm_x4(bk[0], bk[1], bk[2], bk[3], &Kc[row * 72 + ko]);
                    mma16h(s0h, qf[ks], bk);
                    mma16h(s1h, qf[ks], bk + 2);
                }
                int row_lo = q0 + rb + g;
                int row_hi = row_lo + 8;
                int col0 = k0 + (2 * pp) * 8 + 2 * t4;
                pa[pp][0] = ex2h2(addh2(s0h[0], mk_mask(col0, row_lo)));
                pa[pp][1] = ex2h2(addh2(s0h[1], mk_mask(col0, row_hi)));
                int col1 = col0 + 8;
                pa[pp][2] = ex2h2(addh2(s1h[0], mk_mask(col1, row_lo)));
                pa[pp][3] = ex2h2(addh2(s1h[1], mk_mask(col1, row_hi)));
            }
            // row sums + PV (f32 acc)
            #pragma unroll
            for (int ks = 0; ks < 4; ks++) {
                mma16(lacc, pa[ks], bones);
                #pragma unroll
                for (int p = 0; p < 4; p++) {
                    uint32_t b[4];
                    int krow = ks * 16 + (mi & 1) * 8 + mr;
                    int col  = (2 * p + (mi >> 1)) * 8;
                    ldsm_x4_trans(b[0], b[1], b[2], b[3], &Vc[krow * 72 + col]);
                    mma16(o[2*p],     pa[ks], b);
                    mma16(o[2*p + 1], pa[ks], b + 2);
                }
            }
        }

        CP_WAIT(0);
        __syncthreads();
    }

    // normalize + write (lacc[0] = rowsum row g, lacc[2] = row g+8)
    {
        float inv_lo = 1.f / lacc[0];
        float inv_hi = 1.f / lacc[2];
        int row = q0 + rb + g;
        #pragma unroll
        for (int nf = 0; nf < 8; nf++) {
            int d = nf * 8 + 2 * t4;
            *(uint32_t*)&ob[(size_t)row * DHD + d] =
                h2u(o[nf][0] * inv_lo, o[nf][1] * inv_lo);
            *(uint32_t*)&ob[(size_t)(row + 8) * DHD + d] =
                h2u(o[nf][2] * inv_hi, o[nf][3] * inv_hi);
        }
    }
}

// ---------------------------------------------------------------------------
// Kernel 3: output projection, fp16, K-chunk 64, 3-stage cp.async.
// 256 threads (8 warps, 2x4; warp tile 64x32). (unchanged)
// ---------------------------------------------------------------------------
#define OP_BUF (128*72)
#define OPROJ_SMEM (3 * 2 * OP_BUF * (int)sizeof(__half))   // 110592

__global__ __launch_bounds__(256, 2) void oproj_kernel(const float* __restrict__ bo,
                                                       float* __restrict__ out)
{
    const int m0 = blockIdx.x * 128;
    const int n0 = blockIdx.y * 128;

    extern __shared__ __half smh[];
    __half* As = smh;                  // [3][128][72]
    __half* Bt = smh + 3 * OP_BUF;     // [3][128][72]

    const int tid  = threadIdx.x;
    const int wid  = tid >> 5, lane = tid & 31;
    const int wm   = wid >> 2, wn = wid & 3;
    const int g    = lane >> 2, t4 = lane & 3;
    const int mi   = lane >> 3, mr = lane & 7;

    float c[4][4][4] = {};

    auto stage = [&](int buf, int hc) {
        __half* Ab = As + buf * OP_BUF;
        __half* Bb = Bt + buf * OP_BUF;
        #pragma unroll
        for (int i = 0; i < 4; i++) {
            int f = tid + 256 * i;
            int r = f >> 3, q = (f & 7) * 8;
            int m = m0 + r;
            int b = m >> 11, t = m & (TT - 1);
            cp16(&Ab[r * 72 + q],
                 &g_o[((size_t)(b * HH + hc) * TT + t) * DHD + q]);
            cp16(&Bb[r * 72 + q],
                 &g_woh[(size_t)(n0 + r) * CC + hc * 64 + q]);
        }
    };

    stage(0, 0); CP_COMMIT();
    stage(1, 1); CP_COMMIT();

    int cur = 0, nxt = 2;
    for (int t = 0; t < 16; t++) {
        if (t < 15) { CP_WAIT(1); } else { CP_WAIT(0); }
        __syncthreads();
        if (t + 2 < 16) { stage(nxt, t + 2); CP_COMMIT(); }

        const __half* Ab = As + cur * OP_BUF;
        const __half* Bb = Bt + cur * OP_BUF;
        #pragma unroll
        for (int ks = 0; ks < 4; ks++) {
            uint32_t a[4][4], b[4][2];
            #pragma unroll
            for (int mf = 0; mf < 4; mf++) {
                int row = wm * 64 + mf * 16 + (mi & 1) * 8 + mr;
                int ko  = ks * 16 + (mi >> 1) * 8;
                ldsm_x4(a[mf][0], a[mf][1], a[mf][2], a[mf][3], &Ab[row * 72 + ko]);
            }
            #pragma unroll
            for (int p = 0; p < 2; p++) {
                int row = wn * 32 + p * 16 + (mi >> 1) * 8 + mr;
                int ko  = ks * 16 + (mi & 1) * 8;
                ldsm_x4(b[2*p][0], b[2*p][1], b[2*p+1][0], b[2*p+1][1],
                        &Bb[row * 72 + ko]);
            }
            #pragma unroll
            for (int mf = 0; mf < 4; mf++)
                #pragma unroll
                for (int nf = 0; nf < 4; nf++)
                    mma16(c[mf][nf], a[mf], b[nf]);
        }
        cur = (cur == 2) ? 0 : cur + 1;
        nxt = (nxt == 2) ? 0 : nxt + 1;
    }

    #pragma unroll
    for (int mf = 0; mf < 4; mf++) {
        int m1 = m0 + wm * 64 + mf * 16 + g;
        #pragma unroll
        for (int nf = 0; nf < 4; nf++) {
            int col = n0 + wn * 32 + nf * 8 + 2 * t4;
            float2 bb = *(const float2*)&bo[col];
            *(float2*)&out[(size_t)m1 * CC + col] =
                make_float2(c[mf][nf][0] + bb.x, c[mf][nf][1] + bb.y);
            *(float2*)&out[(size_t)(m1 + 8) * CC + col] =
                make_float2(c[mf][nf][2] + bb.x, c[mf][nf][3] + bb.y);
        }
    }
}

// ---------------------------------------------------------------------------
extern "C" void kernel_launch(void* const* d_in, const int* in_sizes, int n_in,
                              void* d_out, int out_size)
{
    const float* x  = (const float*)d_in[0];
    const float* Wq = (const float*)d_in[1];
    const float* Wk = (const float*)d_in[2];
    const float* Wv = (const float*)d_in[3];
    const float* Wo = (const float*)d_in[4];
    const float* bo = (const float*)d_in[5];
    float* out = (float*)d_out;

    static int attr_done = 0;
    if (!attr_done) {
        cudaFuncSetAttribute(qkv_kernel,
                             cudaFuncAttributeMaxDynamicSharedMemorySize, QKV_SMEM);
        cudaFuncSetAttribute(attn_kernel,
                             cudaFuncAttributeMaxDynamicSharedMemorySize, ATTN_SMEM);
        cudaFuncSetAttribute(oproj_kernel,
                             cudaFuncAttributeMaxDynamicSharedMemorySize, OPROJ_SMEM);
        attr_done = 1;
    }

    cvt_all<<<NTOT / (256 * 16), 256>>>(x, Wq, Wk, Wv, Wo);
    qkv_kernel<<<dim3(MM / 128, 24), 256, QKV_SMEM>>>();
    attn_kernel<<<dim3(TT / 128, BB * HH), 256, ATTN_SMEM>>>();
    oproj_kernel<<<dim3(MM / 128, CC / 128), 256, OPROJ_SMEM>>>(bo, out);
}